// round 11
// baseline (speedup 1.0000x reference)
#include <cuda_runtime.h>

#define Bsz 2
#define Nn  4096
#define Cc  192
#define Hh  8
#define Dd  24
#define JCH 32                  // j-rows per task (two blocks per SM, uniform)
#define NBLK 256
#define NT   512

#define FPSCALE 4194304.0f      // 2^22
#define FPINV   (1.0f / 4194304.0f)

// Scratch (__device__ globals; no allocations allowed)
__device__ float g_wksum[Hh * Cc];
__device__ unsigned long long g_Ufp[Bsz * Cc * Hh];   // [b][t'*8 + h]
__device__ unsigned long long g_zfp[Bsz * Hh];
__device__ unsigned int g_ac_done = 0;

// ---------------------------------------------------------------------------
// Prelude: wksum; zero fixed-point accumulators + flag (graph edge orders this).
// ---------------------------------------------------------------------------
__global__ void k_pre(const float* __restrict__ Wqkv) {
    int gid = blockIdx.x * 512 + threadIdx.x;          // 0..1535
    g_Ufp[gid] = 0ull;
    g_Ufp[gid + 1536] = 0ull;
    if (gid < Bsz * Hh) g_zfp[gid] = 0ull;
    if (gid == 0) g_ac_done = 0;
    int h = gid / Cc, c = gid - h * Cc;
    const float* base = Wqkv + (size_t)(Cc + h * Dd) * Cc + c;
    float s = 0.f;
#pragma unroll
    for (int d = 0; d < Dd; d++) s += base[(size_t)d * Cc];
    g_wksum[gid] = s;
}

// ---------------------------------------------------------------------------
__global__ __launch_bounds__(NT, 2)
void fused_kernel(const float* __restrict__ x,
                  const float* __restrict__ Wqkv,
                  const float* __restrict__ Wproj,
                  const float* __restrict__ bproj,
                  const float* __restrict__ scale,
                  float4* __restrict__ out) {
    __shared__ __align__(16) float s_ws[Hh * Cc];       // 1536
    __shared__ __align__(16) float s_et[JCH * Hh];      // 256, transposed [j][h]
    __shared__ __align__(16) float s_part[Hh * Cc];     // jg1 xw partial
    __shared__ __align__(16) float s_comb[Hh * Cc];     // combined xw
    __shared__ __align__(16) float s_ov[Cc];
    __shared__ float s_invz[Bsz * Hh];
    __shared__ __align__(16) float s_y[Bsz * Cc];

    const int tid  = threadIdx.x;
    const int bid  = blockIdx.x;
    const int warp = tid >> 5;                          // 0..15
    const int lane = tid & 31;

    const int b     = bid >> 7;                         // 128 chunks per batch
    const int chunk = bid & 127;
    const int j0    = chunk * JCH;

    // ---- stage wksum ----
    if (tid < 384) ((float4*)s_ws)[tid] = ((const float4*)g_wksum)[tid];
    __syncthreads();

    // ---- e-phase: 16 warps x 2 rows; warp-split 192-dot (x in regs) ----
    {
        const float sc = __ldg(scale);
#pragma unroll
        for (int r = 0; r < 2; r++) {
            const int jj = warp * 2 + r;                // 0..31
            const float* xr = x + (size_t)(b * Nn + j0 + jj) * Cc;
            float xv[6];
#pragma unroll
            for (int i = 0; i < 6; i++) xv[i] = xr[lane + 32 * i];
#pragma unroll
            for (int h = 0; h < Hh; h++) {
                float p = 0.f;
#pragma unroll
                for (int i = 0; i < 6; i++) p += xv[i] * s_ws[h * Cc + lane + 32 * i];
#pragma unroll
                for (int o = 16; o > 0; o >>= 1) p += __shfl_down_sync(0xffffffffu, p, o);
                if (lane == 0) s_et[jj * Hh + h] = __expf(p * sc);
            }
        }
    }
    __syncthreads();

    // ---- xw partials (threads 0..383, 2 jg x 16 rows) + Z (warps 12..15) ----
    {
        const int jg = tid / Cc;
        const int c  = tid - jg * Cc;
        float acc[Hh];
#pragma unroll
        for (int h = 0; h < Hh; h++) acc[h] = 0.f;

        if (tid < 2 * Cc) {
            const float* xp = x + ((size_t)(b * Nn + j0 + jg * 16)) * Cc + c;
#pragma unroll 4
            for (int q = 0; q < 16; q++) {
                float xv = xp[(size_t)q * Cc];          // L1-hot from e phase
                const int wj = jg * 16 + q;
                float4 e0 = ((const float4*)s_et)[wj * 2];      // h 0..3 (broadcast)
                float4 e1 = ((const float4*)s_et)[wj * 2 + 1];  // h 4..7
                acc[0] += e0.x * xv; acc[1] += e0.y * xv;
                acc[2] += e0.z * xv; acc[3] += e0.w * xv;
                acc[4] += e1.x * xv; acc[5] += e1.y * xv;
                acc[6] += e1.z * xv; acc[7] += e1.w * xv;
            }
        } else if (warp >= 12) {                        // Z: 4 warps x 2 heads
            const int h = (warp - 12) * 2 + (lane >> 4);
            const int l = lane & 15;
            float z = s_et[l * Hh + h] + s_et[(l + 16) * Hh + h];
#pragma unroll
            for (int o = 8; o > 0; o >>= 1) z += __shfl_xor_sync(0xffffffffu, z, o);
            if (l == 0)
                atomicAdd(&g_zfp[b * Hh + h],
                          (unsigned long long)__float2ll_rn(z * FPSCALE));
        }
        __syncthreads();
        if (jg == 1) {
#pragma unroll
            for (int h = 0; h < Hh; h++) s_part[h * Cc + c] = acc[h];
        }
        __syncthreads();
        if (jg == 0) {
#pragma unroll
            for (int h = 0; h < Hh; h++) s_comb[h * Cc + c] = acc[h] + s_part[h * Cc + c];
        }
    }
    __syncthreads();

    // ---- ovu partial: 192 dots of 192 (16 warps x 12 t, warp-split) ----
    {
#pragma unroll
        for (int r = 0; r < 12; r++) {
            const int t = warp * 12 + r;                // 0..191
            const int h = t / Dd;
            const float* wv  = Wqkv + (size_t)(2 * Cc + t) * Cc;
            const float* xwh = s_comb + h * Cc;
            float p = 0.f;
#pragma unroll
            for (int i = 0; i < 6; i++) p += xwh[lane + 32 * i] * wv[lane + 32 * i];
#pragma unroll
            for (int o = 16; o > 0; o >>= 1) p += __shfl_down_sync(0xffffffffu, p, o);
            if (lane == 0) s_ov[t] = p;
        }
    }
    __syncthreads();

    // ---- U partial: o = t'*8 + h; 3 outputs/thread; fixed-point atomics ----
    {
#pragma unroll
        for (int k = 0; k < 3; k++) {
            const int o  = tid + k * NT;                // 0..1535
            const int tp = o >> 3, h = o & 7;
            const float4* wp = (const float4*)(Wproj + (size_t)tp * Cc + h * Dd);
            const float4* ov = (const float4*)(s_ov + h * Dd);
            float s = 0.f;
#pragma unroll
            for (int q = 0; q < 6; q++) {
                float4 w4 = wp[q], o4 = ov[q];
                s += w4.x * o4.x + w4.y * o4.y + w4.z * o4.z + w4.w * o4.w;
            }
            atomicAdd(&g_Ufp[b * 1536 + o],
                      (unsigned long long)__float2ll_rn(s * FPSCALE));
        }
    }
    __threadfence();
    __syncthreads();
    if (tid == 0) atomicAdd(&g_ac_done, 1u);

    // ---- single arrival-spin sync ----
    if (tid == 0) {
        volatile unsigned int* p = &g_ac_done;
        while (*p < (unsigned)NBLK) __nanosleep(64);
    }
    __syncthreads();
    __threadfence();

    // ---- every block redundantly computes y (pure function of U,Z) ----
    if (tid < Bsz * Hh)
        s_invz[tid] = 1.f / ((float)(long long)g_zfp[tid] * FPINV);
    __syncthreads();
    if (tid < Bsz * Cc) {
        const int b2 = tid / Cc, tp = tid - b2 * Cc;
        const unsigned long long* up = g_Ufp + b2 * 1536 + tp * 8;
        float s = bproj[tp];
#pragma unroll
        for (int h = 0; h < Hh; h++)
            s += s_invz[b2 * Hh + h] * ((float)(long long)up[h] * FPINV);
        s_y[tid] = s;
    }
    __syncthreads();

    // ---- broadcast: 256 * 1536 = 393216 float4 ----
    {
        const float4* sy4 = (const float4*)s_y;
        const int base = bid * 1536;
#pragma unroll
        for (int k = 0; k < 3; k++) {
            int g  = base + k * NT + tid;
            int r  = g % 48;
            int bb = (g >= Nn * 48) ? 1 : 0;
            out[g] = sy4[bb * 48 + r];
        }
    }
}

extern "C" void kernel_launch(void* const* d_in, const int* in_sizes, int n_in,
                              void* d_out, int out_size) {
    const float* x     = (const float*)d_in[0];
    const float* Wqkv  = (const float*)d_in[1];
    const float* Wproj = (const float*)d_in[2];
    const float* bproj = (const float*)d_in[3];
    const float* scale = (const float*)d_in[4];

    k_pre<<<3, 512>>>(Wqkv);
    fused_kernel<<<NBLK, NT>>>(x, Wqkv, Wproj, bproj, scale, (float4*)d_out);
}

// round 12
// speedup vs baseline: 1.1963x; 1.1963x over previous
#include <cuda_runtime.h>

#define Bsz 2
#define Nn  4096
#define Cc  192
#define Hh  8
#define Dd  24
#define JCH 64                  // j-rows per task (one block per SM, uniform)
#define NCH 64
#define NBLK 128
#define NT   512

#define FPSCALE 4194304.0f      // 2^22
#define FPINV   (1.0f / 4194304.0f)

// Scratch (__device__ globals; no allocations allowed)
__device__ float g_wksum[Hh * Cc];
__device__ unsigned long long g_Ufp[Bsz * Cc * Hh];   // [b][t'*8 + h]
__device__ unsigned long long g_zfp[Bsz * Hh];
__device__ unsigned int g_ac_done = 0;

// ---------------------------------------------------------------------------
// Prelude: wksum; zero fixed-point accumulators + flag (graph edge orders this).
// ---------------------------------------------------------------------------
__global__ void k_pre(const float* __restrict__ Wqkv) {
    int gid = blockIdx.x * 512 + threadIdx.x;          // 0..1535
    g_Ufp[gid] = 0ull;
    g_Ufp[gid + 1536] = 0ull;
    if (gid < Bsz * Hh) g_zfp[gid] = 0ull;
    if (gid == 0) g_ac_done = 0;
    int h = gid / Cc, c = gid - h * Cc;
    const float* base = Wqkv + (size_t)(Cc + h * Dd) * Cc + c;
    float s = 0.f;
#pragma unroll
    for (int d = 0; d < Dd; d++) s += base[(size_t)d * Cc];
    g_wksum[gid] = s;
}

// ---------------------------------------------------------------------------
__global__ __launch_bounds__(NT, 1)
void fused_kernel(const float* __restrict__ x,
                  const float* __restrict__ Wqkv,
                  const float* __restrict__ Wproj,
                  const float* __restrict__ bproj,
                  const float* __restrict__ scale,
                  float4* __restrict__ out) {
    __shared__ float s_ws[Hh * Cc];                   // 1536
    __shared__ float s_e[Hh * JCH];                   // 512
    __shared__ __align__(16) float s_comb[Hh * Cc];   // 1536 (chunk xw)
    __shared__ __align__(16) float s_ov[Cc];          // 192
    __shared__ float s_invz[Bsz * Hh];                // 16
    __shared__ __align__(16) float s_y[Bsz * Cc];     // 384

    const int tid  = threadIdx.x;
    const int bid  = blockIdx.x;
    const int warp = tid >> 5;
    const int lane = tid & 31;

    const int b     = bid >> 6;                       // 64 chunks per batch
    const int chunk = bid & 63;
    const int j0    = chunk * JCH;

    // ---- stage wksum ----
    if (tid < 384) ((float4*)s_ws)[tid] = ((const float4*)g_wksum)[tid];
    __syncthreads();

    // ---- e for 64 rows: 16 warps x 4 rows ----
    {
        const float sc = __ldg(scale);
#pragma unroll
        for (int r = 0; r < 4; r++) {
            const int jj = warp * 4 + r;
            const float* xr = x + (size_t)(b * Nn + j0 + jj) * Cc;
            float xv[6];
#pragma unroll
            for (int i = 0; i < 6; i++) xv[i] = xr[lane + 32 * i];
#pragma unroll
            for (int h = 0; h < Hh; h++) {
                float p = 0.f;
#pragma unroll
                for (int i = 0; i < 6; i++) p += xv[i] * s_ws[h * Cc + lane + 32 * i];
#pragma unroll
                for (int o = 16; o > 0; o >>= 1) p += __shfl_down_sync(0xffffffffu, p, o);
                if (lane == 0) s_e[h * JCH + jj] = __expf(p * sc);
            }
        }
    }
    __syncthreads();

    // ---- xw partial (threads 0..383) + Z atomics + WEIGHT PREFETCH (warps 12..15) ----
    {
        const int jg = tid / Cc;
        const int c  = tid - jg * Cc;
        float acc[Hh];
#pragma unroll
        for (int h = 0; h < Hh; h++) acc[h] = 0.f;

        if (tid < 2 * Cc) {
            const float* xp = x + ((size_t)(b * Nn + j0 + jg * 32)) * Cc + c;
#pragma unroll 8
            for (int q = 0; q < 32; q++) {
                float xv = xp[(size_t)q * Cc];       // L1-hot from e phase
                int wj = jg * 32 + q;
#pragma unroll
                for (int h = 0; h < Hh; h++) acc[h] += s_e[h * JCH + wj] * xv;
            }
        } else if (warp >= 12) {                      // Z partial -> global fp atomic
            int h = (warp - 12) * 2 + (lane >> 4);
            int l = lane & 15;
            const float* eh = s_e + h * JCH;
            float z = eh[l] + eh[16 + l] + eh[32 + l] + eh[48 + l];
#pragma unroll
            for (int o = 8; o > 0; o >>= 1) z += __shfl_xor_sync(0xffffffffu, z, o);
            if (l == 0)
                atomicAdd(&g_zfp[b * Hh + h],
                          (unsigned long long)__float2ll_rn(z * FPSCALE));

            // Prefetch Wqkv V-block (147KB) + Wproj (147KB) into L1 so the
            // ov/U phases hit L1 (~39cyc) instead of L2 (~250cyc). 1152 lines
            // each; 4 warps x 32 lanes x 9 lines. asm volatile => not elided.
            {
                const int pidx = (warp - 12) * 32 + lane;          // 0..127
                const char* wvb = (const char*)(Wqkv + (size_t)2 * Cc * Cc);
                const char* wpb = (const char*)Wproj;
                float t1, t2;
#pragma unroll
                for (int q = 0; q < 9; q++) {
                    const size_t off = ((size_t)(q * 128 + pidx)) * 128;
                    asm volatile("ld.global.nc.f32 %0, [%1];" : "=f"(t1) : "l"(wvb + off));
                    asm volatile("ld.global.nc.f32 %0, [%1];" : "=f"(t2) : "l"(wpb + off));
                }
            }
        }
        __syncthreads();
        if (jg == 1) {
#pragma unroll
            for (int h = 0; h < Hh; h++) s_comb[h * Cc + c] = acc[h];
        }
        __syncthreads();
        if (jg == 0) {
#pragma unroll
            for (int h = 0; h < Hh; h++) s_comb[h * Cc + c] += acc[h];
        }
    }
    __syncthreads();

    // ---- ovu partial: 192 dots of 192 (16 warps x 12 t) ----
    {
#pragma unroll
        for (int r = 0; r < 12; r++) {
            const int t = warp * 12 + r;              // 0..191
            const int h = t / Dd;
            const float* wv = Wqkv + (size_t)(2 * Cc + t) * Cc;
            const float* xwh = s_comb + h * Cc;
            float p = 0.f;
#pragma unroll
            for (int i = 0; i < 6; i++) p += xwh[lane + 32 * i] * wv[lane + 32 * i];
#pragma unroll
            for (int o = 16; o > 0; o >>= 1) p += __shfl_down_sync(0xffffffffu, p, o);
            if (lane == 0) s_ov[t] = p;
        }
    }
    __syncthreads();

    // ---- U partial: o = t'*8 + h; 3 outputs/thread; fixed-point atomics ----
    {
#pragma unroll
        for (int k = 0; k < 3; k++) {
            int o  = tid + k * NT;                    // 0..1535
            int tp = o >> 3, h = o & 7;
            const float4* wp = (const float4*)(Wproj + (size_t)tp * Cc + h * Dd);
            const float4* ov = (const float4*)(s_ov + h * Dd);
            float s = 0.f;
#pragma unroll
            for (int q = 0; q < 6; q++) {
                float4 w4 = wp[q], o4 = ov[q];
                s += w4.x * o4.x + w4.y * o4.y + w4.z * o4.z + w4.w * o4.w;
            }
            atomicAdd(&g_Ufp[b * 1536 + o],
                      (unsigned long long)__float2ll_rn(s * FPSCALE));
        }
    }
    __threadfence();
    __syncthreads();
    if (tid == 0) atomicAdd(&g_ac_done, 1u);

    // ---- single arrival-spin sync ----
    if (tid == 0) {
        volatile unsigned int* p = &g_ac_done;
        while (*p < (unsigned)NBLK) __nanosleep(64);
    }
    __syncthreads();
    __threadfence();

    // ---- every block redundantly computes y (pure function of U,Z) ----
    if (tid < Bsz * Hh)
        s_invz[tid] = 1.f / ((float)(long long)g_zfp[tid] * FPINV);
    __syncthreads();
    if (tid < Bsz * Cc) {
        const int b2 = tid / Cc, tp = tid - b2 * Cc;
        const unsigned long long* up = g_Ufp + b2 * 1536 + tp * 8;
        float s = bproj[tp];
#pragma unroll
        for (int h = 0; h < Hh; h++)
            s += s_invz[b2 * Hh + h] * ((float)(long long)up[h] * FPINV);
        s_y[tid] = s;
    }
    __syncthreads();

    // ---- broadcast: 128 * 3072 = 393216 float4 ----
    {
        const float4* sy4 = (const float4*)s_y;
        const int base = bid * 3072;
#pragma unroll
        for (int k = 0; k < 6; k++) {
            int g  = base + k * NT + tid;
            int r  = g % 48;
            int bb = (g >= Nn * 48) ? 1 : 0;
            out[g] = sy4[bb * 48 + r];
        }
    }
}

extern "C" void kernel_launch(void* const* d_in, const int* in_sizes, int n_in,
                              void* d_out, int out_size) {
    const float* x     = (const float*)d_in[0];
    const float* Wqkv  = (const float*)d_in[1];
    const float* Wproj = (const float*)d_in[2];
    const float* bproj = (const float*)d_in[3];
    const float* scale = (const float*)d_in[4];

    k_pre<<<3, 512>>>(Wqkv);
    fused_kernel<<<NBLK, NT>>>(x, Wqkv, Wproj, bproj, scale, (float4*)d_out);
}

// round 13
// speedup vs baseline: 1.2912x; 1.0793x over previous
#include <cuda_runtime.h>

#define Bsz 2
#define Nn  4096
#define Cc  192
#define Hh  8
#define Dd  24
#define JCH 64                  // j-rows per task (one block per SM, uniform)
#define NBLK 128
#define NT   512

#define FPSCALE 4194304.0f      // 2^22
#define FPINV   (1.0f / 4194304.0f)

// Scratch (__device__ globals; no allocations allowed)
__device__ float g_wksum[Hh * Cc];
__device__ unsigned long long g_Ufp[Bsz * Cc * Hh];   // [b][t'*8 + h]
__device__ unsigned long long g_zfp[Bsz * Hh];
__device__ unsigned int g_ac_done = 0;

// ---------------------------------------------------------------------------
// Prelude: wksum; zero fixed-point accumulators + flag (graph edge orders this).
// ---------------------------------------------------------------------------
__global__ void k_pre(const float* __restrict__ Wqkv) {
    int gid = blockIdx.x * 512 + threadIdx.x;          // 0..1535
    g_Ufp[gid] = 0ull;
    g_Ufp[gid + 1536] = 0ull;
    if (gid < Bsz * Hh) g_zfp[gid] = 0ull;
    if (gid == 0) g_ac_done = 0;
    int h = gid / Cc, c = gid - h * Cc;
    const float* base = Wqkv + (size_t)(Cc + h * Dd) * Cc + c;
    float s = 0.f;
#pragma unroll
    for (int d = 0; d < Dd; d++) s += base[(size_t)d * Cc];
    g_wksum[gid] = s;
}

// ---------------------------------------------------------------------------
__global__ __launch_bounds__(NT, 1)
void fused_kernel(const float* __restrict__ x,
                  const float* __restrict__ Wqkv,
                  const float* __restrict__ Wproj,
                  const float* __restrict__ bproj,
                  const float* __restrict__ scale,
                  float4* __restrict__ out) {
    __shared__ float s_ws[Hh * Cc];                   // 1536
    __shared__ float s_e[Hh * JCH];                   // 512
    __shared__ __align__(16) float s_comb[Hh * Cc];   // 1536 (chunk xw)
    __shared__ __align__(16) float s_ov[Cc];          // 192
    __shared__ float s_invz[Bsz * Hh];                // 16
    __shared__ __align__(16) float s_y[Bsz * Cc];     // 384

    const int tid  = threadIdx.x;
    const int bid  = blockIdx.x;
    const int warp = tid >> 5;
    const int lane = tid & 31;
    const unsigned FULL = 0xffffffffu;

    const int b     = bid >> 6;                       // 64 chunks per batch
    const int chunk = bid & 63;
    const int j0    = chunk * JCH;

    // ---- stage wksum ----
    if (tid < 384) ((float4*)s_ws)[tid] = ((const float4*)g_wksum)[tid];
    __syncthreads();

    // ---- e for 64 rows: 16 warps x 4 rows; 8-head butterfly (9 shfl/row) ----
    {
        const float sc = __ldg(scale);
#pragma unroll
        for (int r = 0; r < 4; r++) {
            const int jj = warp * 4 + r;
            const float* xr = x + (size_t)(b * Nn + j0 + jj) * Cc;
            float xv[6];
#pragma unroll
            for (int i = 0; i < 6; i++) xv[i] = xr[lane + 32 * i];

            float a[Hh];
#pragma unroll
            for (int h = 0; h < Hh; h++) {
                float p = 0.f;
#pragma unroll
                for (int i = 0; i < 6; i++) p += xv[i] * s_ws[h * Cc + lane + 32 * i];
                a[h] = p;
            }
            // butterfly: mask 1 (8->4)
            const bool m1 = (lane & 1);
            float b0 = (m1 ? a[1] : a[0]) + __shfl_xor_sync(FULL, m1 ? a[0] : a[1], 1);
            float b1 = (m1 ? a[3] : a[2]) + __shfl_xor_sync(FULL, m1 ? a[2] : a[3], 1);
            float b2 = (m1 ? a[5] : a[4]) + __shfl_xor_sync(FULL, m1 ? a[4] : a[5], 1);
            float b3 = (m1 ? a[7] : a[6]) + __shfl_xor_sync(FULL, m1 ? a[6] : a[7], 1);
            // mask 2 (4->2)
            const bool m2 = (lane & 2);
            float c0 = (m2 ? b1 : b0) + __shfl_xor_sync(FULL, m2 ? b0 : b1, 2);
            float c1 = (m2 ? b3 : b2) + __shfl_xor_sync(FULL, m2 ? b2 : b3, 2);
            // mask 4 (2->1): head = lane & 7
            const bool m4 = (lane & 4);
            float d = (m4 ? c1 : c0) + __shfl_xor_sync(FULL, m4 ? c0 : c1, 4);
            // cross-octet sums
            d += __shfl_xor_sync(FULL, d, 8);
            d += __shfl_xor_sync(FULL, d, 16);
            if (lane < 8) s_e[lane * JCH + jj] = __expf(d * sc);
        }
    }
    __syncthreads();

    // ---- xw partial (threads 0..383) + Z fixed-point atomics (warps 12..15) ----
    {
        const int jg = tid / Cc;
        const int c  = tid - jg * Cc;
        float acc[Hh];
#pragma unroll
        for (int h = 0; h < Hh; h++) acc[h] = 0.f;

        if (tid < 2 * Cc) {
            const float* xp = x + ((size_t)(b * Nn + j0 + jg * 32)) * Cc + c;
#pragma unroll 8
            for (int q = 0; q < 32; q++) {
                float xv = xp[(size_t)q * Cc];       // L1-hot from e phase
                int wj = jg * 32 + q;
#pragma unroll
                for (int h = 0; h < Hh; h++) acc[h] += s_e[h * JCH + wj] * xv;
            }
        } else if (warp >= 12) {                      // Z partial -> global fp atomic
            int h = (warp - 12) * 2 + (lane >> 4);
            int l = lane & 15;
            const float* eh = s_e + h * JCH;
            float z = eh[l] + eh[16 + l] + eh[32 + l] + eh[48 + l];
#pragma unroll
            for (int o = 8; o > 0; o >>= 1) z += __shfl_xor_sync(FULL, z, o);
            if (l == 0)
                atomicAdd(&g_zfp[b * Hh + h],
                          (unsigned long long)__float2ll_rn(z * FPSCALE));
        }
        __syncthreads();
        if (jg == 1) {
#pragma unroll
            for (int h = 0; h < Hh; h++) s_comb[h * Cc + c] = acc[h];
        }
        __syncthreads();
        if (jg == 0) {
#pragma unroll
            for (int h = 0; h < Hh; h++) s_comb[h * Cc + c] += acc[h];
        }
    }
    __syncthreads();

    // ---- ovu partial: 192 dots of 192 (16 warps x 12 t) ----
    {
#pragma unroll
        for (int r = 0; r < 12; r++) {
            const int t = warp * 12 + r;              // 0..191
            const int h = t / Dd;
            const float* wv = Wqkv + (size_t)(2 * Cc + t) * Cc;
            const float* xwh = s_comb + h * Cc;
            float p = 0.f;
#pragma unroll
            for (int i = 0; i < 6; i++) p += xwh[lane + 32 * i] * wv[lane + 32 * i];
#pragma unroll
            for (int o = 16; o > 0; o >>= 1) p += __shfl_down_sync(FULL, p, o);
            if (lane == 0) s_ov[t] = p;
        }
    }
    __syncthreads();

    // ---- U partial: o = t'*8 + h; 3 outputs/thread; fixed-point atomics ----
    {
#pragma unroll
        for (int k = 0; k < 3; k++) {
            int o  = tid + k * NT;                    // 0..1535
            int tp = o >> 3, h = o & 7;
            const float4* wp = (const float4*)(Wproj + (size_t)tp * Cc + h * Dd);
            const float4* ov = (const float4*)(s_ov + h * Dd);
            float s = 0.f;
#pragma unroll
            for (int q = 0; q < 6; q++) {
                float4 w4 = wp[q], o4 = ov[q];
                s += w4.x * o4.x + w4.y * o4.y + w4.z * o4.z + w4.w * o4.w;
            }
            atomicAdd(&g_Ufp[b * 1536 + o],
                      (unsigned long long)__float2ll_rn(s * FPSCALE));
        }
    }
    __threadfence();
    __syncthreads();
    if (tid == 0) atomicAdd(&g_ac_done, 1u);

    // ---- single arrival-spin sync ----
    if (tid == 0) {
        volatile unsigned int* p = &g_ac_done;
        while (*p < (unsigned)NBLK) __nanosleep(64);
    }
    __syncthreads();
    __threadfence();

    // ---- every block redundantly computes y (pure function of U,Z) ----
    if (tid < Bsz * Hh)
        s_invz[tid] = 1.f / ((float)(long long)g_zfp[tid] * FPINV);
    __syncthreads();
    if (tid < Bsz * Cc) {
        const int b2 = tid / Cc, tp = tid - b2 * Cc;
        const unsigned long long* up = g_Ufp + b2 * 1536 + tp * 8;
        float s = bproj[tp];
#pragma unroll
        for (int h = 0; h < Hh; h++)
            s += s_invz[b2 * Hh + h] * ((float)(long long)up[h] * FPINV);
        s_y[tid] = s;
    }
    __syncthreads();

    // ---- broadcast: 128 * 3072 = 393216 float4 ----
    {
        const float4* sy4 = (const float4*)s_y;
        const int base = bid * 3072;
#pragma unroll
        for (int k = 0; k < 6; k++) {
            int g  = base + k * NT + tid;
            int r  = g % 48;
            int bb = (g >= Nn * 48) ? 1 : 0;
            out[g] = sy4[bb * 48 + r];
        }
    }
}

extern "C" void kernel_launch(void* const* d_in, const int* in_sizes, int n_in,
                              void* d_out, int out_size) {
    const float* x     = (const float*)d_in[0];
    const float* Wqkv  = (const float*)d_in[1];
    const float* Wproj = (const float*)d_in[2];
    const float* bproj = (const float*)d_in[3];
    const float* scale = (const float*)d_in[4];

    k_pre<<<3, 512>>>(Wqkv);
    fused_kernel<<<NBLK, NT>>>(x, Wqkv, Wproj, bproj, scale, (float4*)d_out);
}